// round 12
// baseline (speedup 1.0000x reference)
#include <cuda_runtime.h>
#include <cuda_fp16.h>
#include <cstdint>

#define MROWS 8192   // B*N tokens
#define KPROT 8192   // prototypes
#define DDIM  768
#define INV_TT (1.0f/0.07f)
#define INV_ST 10.0f
#define SK_EPS 1e-8f
#define SHIFT  9.0f
#define NKTILE 2080  // koleo triangular tiles (64*65/2)
#define KCHUNK 520   // per pass launch

// ---------------- scratch (static device globals; no allocation) -------------
static __device__ __align__(16) __half g_Et[(size_t)MROWS * KPROT]; // exp(Lt/tt - shift)
static __device__ __align__(16) __half g_th[MROWS * DDIM];
static __device__ __align__(16) __half g_sh[MROWS * DDIM];
static __device__ __align__(16) __half g_whr[KPROT * DDIM];
static __device__ __align__(16) __half g_whn[KPROT * DDIM];
static __device__ float  g_S[KPROT];
static __device__ float  g_r[KPROT];
static __device__ float  g_c[MROWS];
static __device__ float  g_msk[MROWS];
static __device__ int    g_maxd[KPROT];
// per-row loss partials (accumulated by student GEMM epilogue)
static __device__ float  g_rowA[MROWS];
static __device__ float  g_rowB[MROWS];
static __device__ float  g_rowD[MROWS];
static __device__ float  g_rowC[MROWS];
static __device__ float  g_rowF[MROWS];
static __device__ float  g_acc[4];
static __device__ int    g_maskmode;

// ---------------- reductions ---------------------------------------------------
__device__ __forceinline__ float warpSum(float v) {
#pragma unroll
    for (int o = 16; o > 0; o >>= 1) v += __shfl_down_sync(0xffffffffu, v, o);
    return v;
}
__device__ float blockSum(float v) {
    __shared__ float sb[32];
    int lane = threadIdx.x & 31, w = threadIdx.x >> 5;
    v = warpSum(v);
    __syncthreads();
    if (lane == 0) sb[w] = v;
    __syncthreads();
    int nw = (blockDim.x + 31) >> 5;
    v = (threadIdx.x < nw) ? sb[threadIdx.x] : 0.f;
    if (w == 0) v = warpSum(v);
    return v;
}

// ---------------- mask handling -------------------------------------------------
__global__ void detect_mask_kernel(const unsigned char* __restrict__ p) {
    __shared__ int c0, c1, c23;
    if (threadIdx.x == 0) { c0 = 0; c1 = 0; c23 = 0; }
    __syncthreads();
    int l0 = 0, l1 = 0, l23 = 0;
    for (int i = threadIdx.x; i < MROWS; i += blockDim.x) {
        unsigned char b = p[i];
        if (b) { int r = i & 3; if (r == 0) l0++; else if (r == 1) l1++; else l23++; }
    }
    atomicAdd(&c0, l0); atomicAdd(&c1, l1); atomicAdd(&c23, l23);
    __syncthreads();
    if (threadIdx.x == 0) {
        int mode;
        if (c1 == 0 && c23 == 0) mode = (c0 > 0) ? 1 : 0;
        else if (c1 == 0)        mode = 2;
        else                     mode = 0;
        g_maskmode = mode;
    }
}
__global__ void build_mask_kernel(const void* __restrict__ p) {
    int m = blockIdx.x * blockDim.x + threadIdx.x;
    if (m >= MROWS) return;
    int mode = g_maskmode;
    float v;
    if (mode == 1)      v = (((const int*)p)[m] != 0) ? 1.f : 0.f;
    else if (mode == 2) v = (((const float*)p)[m] != 0.f) ? 1.f : 0.f;
    else                v = (((const unsigned char*)p)[m] != 0) ? 1.f : 0.f;
    g_msk[m] = v;
}

__global__ void init_kernel() {
    int i = blockIdx.x * blockDim.x + threadIdx.x;
    if (i < KPROT) { g_S[i] = 0.f; g_r[i] = 1.f; g_maxd[i] = 0; }
    if (i < MROWS) {
        g_c[i] = 1.f;
        g_rowA[i] = 0.f; g_rowB[i] = 0.f; g_rowD[i] = 0.f;
        g_rowC[i] = 0.f; g_rowF[i] = 0.f;
    }
    if (i < 4) { g_acc[i] = 0.f; }
}

// ---------------- normalize: warp-per-row, 3 segments in one launch --------------
__global__ void __launch_bounds__(256)
norm_all_kernel(const float* __restrict__ t, const float* __restrict__ s,
                const float* __restrict__ w) {
    int wid = threadIdx.x >> 5, lane = threadIdx.x & 31;
    int row = blockIdx.x * 8 + wid;
    int seg = blockIdx.y;
    const float* in = (seg == 0) ? t : (seg == 1) ? s : w;
    __half* outN = (seg == 0) ? g_th : (seg == 1) ? g_sh : g_whn;
    const float4* x = (const float4*)(in + (size_t)row * DDIM);
    float4 v[6];
    float ss = 0.f;
#pragma unroll
    for (int i = 0; i < 6; i++) {
        v[i] = x[i * 32 + lane];
        ss += v[i].x * v[i].x + v[i].y * v[i].y + v[i].z * v[i].z + v[i].w * v[i].w;
    }
#pragma unroll
    for (int o = 16; o > 0; o >>= 1) ss += __shfl_xor_sync(0xffffffffu, ss, o);
    float inv = 1.f / fmaxf(sqrtf(ss), 1e-12f);
    uint2* oN = (uint2*)(outN + (size_t)row * DDIM);
#pragma unroll
    for (int i = 0; i < 6; i++) {
        __half2 h0 = __floats2half2_rn(v[i].x * inv, v[i].y * inv);
        __half2 h1 = __floats2half2_rn(v[i].z * inv, v[i].w * inv);
        uint2 u; u.x = *(uint32_t*)&h0; u.y = *(uint32_t*)&h1;
        oN[i * 32 + lane] = u;
    }
    if (seg == 2) {
        uint2* oR = (uint2*)(g_whr + (size_t)row * DDIM);
#pragma unroll
        for (int i = 0; i < 6; i++) {
            __half2 h0 = __floats2half2_rn(v[i].x, v[i].y);
            __half2 h1 = __floats2half2_rn(v[i].z, v[i].w);
            uint2 u; u.x = *(uint32_t*)&h0; u.y = *(uint32_t*)&h1;
            oR[i * 32 + lane] = u;
        }
    }
}

// ---------------- shared fp16 MMA mainloop ----------------------------------------
#define ROWB 80
#define TILEB (128 * ROWB)

__device__ __forceinline__ uint32_t smem_u32(const void* p) {
    uint32_t a;
    asm("{ .reg .u64 t; cvta.to.shared.u64 t, %1; cvt.u32.u64 %0, t; }" : "=r"(a) : "l"(p));
    return a;
}
__device__ __forceinline__ void ldsm_x4(uint32_t& r0, uint32_t& r1, uint32_t& r2, uint32_t& r3,
                                        uint32_t addr) {
    asm volatile("ldmatrix.sync.aligned.m8n8.x4.shared.b16 {%0,%1,%2,%3}, [%4];"
                 : "=r"(r0), "=r"(r1), "=r"(r2), "=r"(r3) : "r"(addr));
}
__device__ __forceinline__ void mma16816(float* c, uint32_t a0, uint32_t a1, uint32_t a2,
                                         uint32_t a3, uint32_t b0, uint32_t b1) {
    asm volatile("mma.sync.aligned.m16n8k16.row.col.f32.f16.f16.f32 "
                 "{%0,%1,%2,%3}, {%4,%5,%6,%7}, {%8,%9}, {%0,%1,%2,%3};"
                 : "+f"(c[0]), "+f"(c[1]), "+f"(c[2]), "+f"(c[3])
                 : "r"(a0), "r"(a1), "r"(a2), "r"(a3), "r"(b0), "r"(b1));
}
__device__ __forceinline__ void cpasync16(uint32_t dst, const void* src) {
    asm volatile("cp.async.cg.shared.global [%0], [%1], 16;" :: "r"(dst), "l"(src) : "memory");
}

__device__ __forceinline__ void run_mainloop(const __half* __restrict__ A,
                                             const __half* __restrict__ B,
                                             uint32_t sb, int m0, int n0,
                                             float acc[4][4][4]) {
    int tid = threadIdx.x, wid = tid >> 5, lane = tid & 31;
    int wm = (wid >> 2) * 64, wn = (wid & 3) * 32;
    uint32_t sA[2] = {sb, sb + TILEB};
    uint32_t sB[2] = {sb + 2 * TILEB, sb + 3 * TILEB};

#pragma unroll
    for (int i = 0; i < 4; i++)
#pragma unroll
        for (int j = 0; j < 4; j++)
#pragma unroll
            for (int q = 0; q < 4; q++) acc[i][j][q] = 0.f;

    const __half* gA = A + (size_t)m0 * DDIM;
    const __half* gB = B + (size_t)n0 * DDIM;
    int r0c = tid >> 2, q0c = tid & 3;
    int r1c = (tid + 256) >> 2, q1c = tid & 3;

    int aRow = wm + (lane & 15);
    int aColB = (lane >> 4) * 16;
    int bRow = wn + (lane & 7) + ((lane >> 4) << 3);
    int bColB = ((lane >> 3) & 1) * 16;

#define LOAD_TILE(buf, kt) do {                                               \
    int koff = (kt) * 32;                                                     \
    cpasync16(sA[buf] + r0c * ROWB + q0c * 16, gA + (size_t)r0c * DDIM + koff + q0c * 8); \
    cpasync16(sB[buf] + r0c * ROWB + q0c * 16, gB + (size_t)r0c * DDIM + koff + q0c * 8); \
    cpasync16(sA[buf] + r1c * ROWB + q1c * 16, gA + (size_t)r1c * DDIM + koff + q1c * 8); \
    cpasync16(sB[buf] + r1c * ROWB + q1c * 16, gB + (size_t)r1c * DDIM + koff + q1c * 8); \
    asm volatile("cp.async.commit_group;" ::: "memory");                      \
} while (0)

    LOAD_TILE(0, 0);
    const int NKT = DDIM / 32;
#pragma unroll 1
    for (int kt = 0; kt < NKT; kt++) {
        int buf = kt & 1;
        if (kt + 1 < NKT) {
            LOAD_TILE(buf ^ 1, kt + 1);
            asm volatile("cp.async.wait_group 1;" ::: "memory");
        } else {
            asm volatile("cp.async.wait_group 0;" ::: "memory");
        }
        __syncthreads();
#pragma unroll
        for (int ks = 0; ks < 2; ks++) {
            uint32_t a[4][4], b[2][4];
#pragma unroll
            for (int mi = 0; mi < 4; mi++)
                ldsm_x4(a[mi][0], a[mi][1], a[mi][2], a[mi][3],
                        sA[buf] + (uint32_t)((aRow + mi * 16) * ROWB + ks * 32 + aColB));
#pragma unroll
            for (int np = 0; np < 2; np++)
                ldsm_x4(b[np][0], b[np][1], b[np][2], b[np][3],
                        sB[buf] + (uint32_t)((bRow + np * 16) * ROWB + ks * 32 + bColB));
#pragma unroll
            for (int mi = 0; mi < 4; mi++)
#pragma unroll
                for (int ni = 0; ni < 4; ni++) {
                    int np = ni >> 1, sel = (ni & 1) * 2;
                    mma16816(acc[mi][ni], a[mi][0], a[mi][1], a[mi][2], a[mi][3],
                             b[np][sel], b[np][sel + 1]);
                }
        }
        __syncthreads();
    }
#undef LOAD_TILE
}

// ---------------- koleo tile (symmetric Wn x Wn^T, row+col max) --------------------
__device__ void koleo_tile(int tbx, int tby, uint8_t* smem) {
    int tid = threadIdx.x, wid = tid >> 5, lane = tid & 31;
    int m0 = tby * 128, n0 = tbx * 128;
    int wm = (wid >> 2) * 64, wn = (wid & 3) * 32;
    float acc[4][4][4];
    run_mainloop(g_whn, g_whn, smem_u32(smem), m0, n0, acc);

    int tr = lane >> 2, tc = (lane & 3) * 2;
    float cm[4][2];
#pragma unroll
    for (int ni = 0; ni < 4; ni++) { cm[ni][0] = -2.f; cm[ni][1] = -2.f; }
#pragma unroll
    for (int mi = 0; mi < 4; mi++) {
        int gr0 = m0 + wm + mi * 16 + tr;
        int gr1 = gr0 + 8;
        float mx0 = -2.f, mx1 = -2.f;
#pragma unroll
        for (int ni = 0; ni < 4; ni++) {
            int gc = n0 + wn + ni * 8 + tc;
            float v0 = (gc == gr0) ? -2.f : acc[mi][ni][0];
            float v1 = (gc + 1 == gr0) ? -2.f : acc[mi][ni][1];
            float v2 = (gc == gr1) ? -2.f : acc[mi][ni][2];
            float v3 = (gc + 1 == gr1) ? -2.f : acc[mi][ni][3];
            mx0 = fmaxf(mx0, fmaxf(v0, v1));
            mx1 = fmaxf(mx1, fmaxf(v2, v3));
            cm[ni][0] = fmaxf(cm[ni][0], fmaxf(v0, v2));
            cm[ni][1] = fmaxf(cm[ni][1], fmaxf(v1, v3));
        }
#pragma unroll
        for (int o = 1; o < 4; o <<= 1) {
            mx0 = fmaxf(mx0, __shfl_xor_sync(0xffffffffu, mx0, o));
            mx1 = fmaxf(mx1, __shfl_xor_sync(0xffffffffu, mx1, o));
        }
        if ((lane & 3) == 0) {
            atomicMax(&g_maxd[gr0], __float_as_int(mx0 + 2.0f));
            atomicMax(&g_maxd[gr1], __float_as_int(mx1 + 2.0f));
        }
    }
#pragma unroll
    for (int ni = 0; ni < 4; ni++) {
        float c0 = cm[ni][0], c1 = cm[ni][1];
#pragma unroll
        for (int o = 4; o < 32; o <<= 1) {
            c0 = fmaxf(c0, __shfl_xor_sync(0xffffffffu, c0, o));
            c1 = fmaxf(c1, __shfl_xor_sync(0xffffffffu, c1, o));
        }
        if (lane < 4) {
            int gc = n0 + wn + ni * 8 + lane * 2;
            atomicMax(&g_maxd[gc], __float_as_int(c0 + 2.0f));
            atomicMax(&g_maxd[gc + 1], __float_as_int(c1 + 2.0f));
        }
    }
}

// triangular linear index -> (bx, by), bx <= by
__device__ __forceinline__ void tri_decode(int t, int& bx, int& by) {
    by = (int)((sqrtf(8.f * t + 1.f) - 1.f) * 0.5f);
    while ((by + 1) * (by + 2) / 2 <= t) by++;
    while (by * (by + 1) / 2 > t) by--;
    bx = t - by * (by + 1) / 2;
}

// ---------------- GEMM0: teacher -> g_Et + fused S1 colsum -------------------------
__global__ void __launch_bounds__(256, 2)
gemm_teacher_kernel() {
    __shared__ __align__(16) uint8_t smem[4 * TILEB];
    int tid = threadIdx.x, wid = tid >> 5, lane = tid & 31;
    int m0 = blockIdx.y * 128, n0 = blockIdx.x * 128;
    int wm = (wid >> 2) * 64, wn = (wid & 3) * 32;
    float acc[4][4][4];
    run_mainloop(g_th, g_whr, smem_u32(smem), m0, n0, acc);

    int tr = lane >> 2, tc = (lane & 3) * 2;
#pragma unroll
    for (int mi = 0; mi < 4; mi++) {
        int gr0 = m0 + wm + mi * 16 + tr;
#pragma unroll
        for (int ni = 0; ni < 4; ni++) {
            int gc = n0 + wn + ni * 8 + tc;
            float e0 = __expf(acc[mi][ni][0] * INV_TT - SHIFT);
            float e1 = __expf(acc[mi][ni][1] * INV_TT - SHIFT);
            float e2 = __expf(acc[mi][ni][2] * INV_TT - SHIFT);
            float e3 = __expf(acc[mi][ni][3] * INV_TT - SHIFT);
            *(__half2*)&g_Et[(size_t)gr0 * KPROT + gc] = __floats2half2_rn(e0, e1);
            *(__half2*)&g_Et[(size_t)(gr0 + 8) * KPROT + gc] = __floats2half2_rn(e2, e3);
            acc[mi][ni][0] = e0; acc[mi][ni][1] = e1;
            acc[mi][ni][2] = e2; acc[mi][ni][3] = e3;
        }
    }
#pragma unroll
    for (int ni = 0; ni < 4; ni++) {
        float s0 = 0.f, s1 = 0.f;
#pragma unroll
        for (int mi = 0; mi < 4; mi++) {
            s0 += acc[mi][ni][0] + acc[mi][ni][2];
            s1 += acc[mi][ni][1] + acc[mi][ni][3];
        }
#pragma unroll
        for (int o = 4; o < 32; o <<= 1) {
            s0 += __shfl_down_sync(0xffffffffu, s0, o);
            s1 += __shfl_down_sync(0xffffffffu, s1, o);
        }
        if (lane < 4) {
            int gc = n0 + wn + ni * 8 + lane * 2;
            atomicAdd(&g_S[gc], s0);
            atomicAdd(&g_S[gc + 1], s1);
        }
    }
}

// ---------------- student GEMM + fused loss epilogue --------------------------------
__global__ void __launch_bounds__(256, 2)
gemm_student_kernel() {
    __shared__ __align__(16) uint8_t smem[4 * TILEB];
    int tid = threadIdx.x, wid = tid >> 5, lane = tid & 31;
    int m0 = blockIdx.y * 128, n0 = blockIdx.x * 128;
    int wm = (wid >> 2) * 64, wn = (wid & 3) * 32;
    float acc[4][4][4];
    run_mainloop(g_sh, g_whr, smem_u32(smem), m0, n0, acc);

    int tr = lane >> 2, tc = (lane & 3) * 2;
#pragma unroll
    for (int mi = 0; mi < 4; mi++) {
        int gr0 = m0 + wm + mi * 16 + tr;
        int gr1 = gr0 + 8;
        float A0 = 0.f, B0 = 0.f, D0 = 0.f, C0 = 0.f, F0 = 0.f;
        float A1 = 0.f, B1 = 0.f, D1 = 0.f, C1 = 0.f, F1 = 0.f;
#pragma unroll
        for (int ni = 0; ni < 4; ni++) {
            int gc = n0 + wn + ni * 8 + tc;
            float2 rr = *(const float2*)&g_r[gc];
            float2 f01 = __half22float2(*(const __half2*)&g_Et[(size_t)gr0 * KPROT + gc]);
            float2 f23 = __half22float2(*(const __half2*)&g_Et[(size_t)gr1 * KPROT + gc]);
            {
                float e0 = f01.x, e1 = f01.y;
                float er0 = e0 * rr.x, er1 = e1 * rr.y;
                float lq0 = __logf(fmaxf(e0, 6e-8f)) + SHIFT;
                float lq1 = __logf(fmaxf(e1, 6e-8f)) + SHIFT;
                float ls0 = acc[mi][ni][0], ls1 = acc[mi][ni][1];
                A0 += er0 + er1;
                B0 = fmaf(er0, lq0, fmaf(er1, lq1, B0));
                D0 += e0 + e1;
                C0 = fmaf(er0, ls0, fmaf(er1, ls1, C0));
                F0 += __expf(ls0 * INV_ST) + __expf(ls1 * INV_ST);
            }
            {
                float e0 = f23.x, e1 = f23.y;
                float er0 = e0 * rr.x, er1 = e1 * rr.y;
                float lq0 = __logf(fmaxf(e0, 6e-8f)) + SHIFT;
                float lq1 = __logf(fmaxf(e1, 6e-8f)) + SHIFT;
                float ls0 = acc[mi][ni][2], ls1 = acc[mi][ni][3];
                A1 += er0 + er1;
                B1 = fmaf(er0, lq0, fmaf(er1, lq1, B1));
                D1 += e0 + e1;
                C1 = fmaf(er0, ls0, fmaf(er1, ls1, C1));
                F1 += __expf(ls0 * INV_ST) + __expf(ls1 * INV_ST);
            }
        }
#define QRED(x) do { x += __shfl_xor_sync(0xffffffffu, x, 1); \
                     x += __shfl_xor_sync(0xffffffffu, x, 2); } while (0)
        QRED(A0); QRED(B0); QRED(D0); QRED(C0); QRED(F0);
        QRED(A1); QRED(B1); QRED(D1); QRED(C1); QRED(F1);
#undef QRED
        if ((lane & 3) == 0) {
            atomicAdd(&g_rowA[gr0], A0); atomicAdd(&g_rowB[gr0], B0);
            atomicAdd(&g_rowD[gr0], D0); atomicAdd(&g_rowC[gr0], C0);
            atomicAdd(&g_rowF[gr0], F0);
            atomicAdd(&g_rowA[gr1], A1); atomicAdd(&g_rowB[gr1], B1);
            atomicAdd(&g_rowD[gr1], D1); atomicAdd(&g_rowC[gr1], C1);
            atomicAdd(&g_rowF[gr1], F1);
        }
    }
}

// ---------------- helpers --------------------------------------------------------
__device__ __forceinline__ void h8_to_f(const uint4& u, float f[8]) {
    __half2 a = *(const __half2*)&u.x, b = *(const __half2*)&u.y;
    __half2 c = *(const __half2*)&u.z, d = *(const __half2*)&u.w;
    float2 fa = __half22float2(a), fb = __half22float2(b);
    float2 fc = __half22float2(c), fd = __half22float2(d);
    f[0] = fa.x; f[1] = fa.y; f[2] = fb.x; f[3] = fb.y;
    f[4] = fc.x; f[5] = fc.y; f[6] = fd.x; f[7] = fd.y;
}

// ---------------- Sinkhorn r-update -------------------------------------------------
__global__ void r_update_kernel() {
    int k = blockIdx.x * blockDim.x + threadIdx.x;
    if (k < KPROT) {
        float r = g_r[k], s = g_S[k];
        g_r[k] = r / (r * s + SK_EPS);
        g_S[k] = 0.f;
    }
}

// ---------------- pass_T + interleaved koleo tiles ----------------------------------
// grid.x = 8739; bids with (x & 15) == 15 run koleo tiles (x>>4), others pass_T rows.
__global__ void __launch_bounds__(256, 2)
passT_koleo_kernel(int rev, int klo) {
    __shared__ __align__(16) uint8_t smem[4 * TILEB];
    int x = blockIdx.x;
    if ((x & 15) == 15) {
        int k = x >> 4;
        if (k >= KCHUNK) return;
        int bx, by;
        tri_decode(klo + k, bx, by);
        koleo_tile(bx, by, smem);
        return;
    }
    int m = x - ((x + 1) >> 4);
    if (m >= MROWS) return;
    if (rev) m = MROWS - 1 - m;
    const uint4* row = (const uint4*)(g_Et + (size_t)m * KPROT);
    float t = 0.f;
    for (int i = threadIdx.x; i < KPROT / 8; i += blockDim.x) {
        uint4 u = row[i];
        float ev[8];
        h8_to_f(u, ev);
        float4 r0 = *(const float4*)(g_r + i * 8);
        float4 r1 = *(const float4*)(g_r + i * 8 + 4);
        t += ev[0] * r0.x + ev[1] * r0.y + ev[2] * r0.z + ev[3] * r0.w
           + ev[4] * r1.x + ev[5] * r1.y + ev[6] * r1.z + ev[7] * r1.w;
    }
    t = blockSum(t);
    if (threadIdx.x == 0) {
        float co = g_c[m];
        g_c[m] = co / (co * t + SK_EPS);
    }
}

// ---------------- pass_S + interleaved koleo tiles ----------------------------------
// grid.x = 1040; odd bids run koleo tiles (x>>1), even bids pass_S blocks (x>>1).
__global__ void __launch_bounds__(256, 2)
passS_koleo_kernel(int rev, int klo) {
    __shared__ __align__(16) uint8_t smem[4 * TILEB];
    __shared__ float cs[64];
    int x = blockIdx.x;
    if (x & 1) {
        int k = x >> 1;
        if (k >= KCHUNK) return;
        int bx, by;
        tri_decode(klo + k, bx, by);
        koleo_tile(bx, by, smem);
        return;
    }
    int p = x >> 1;          // 0..519
    if (p >= 512) return;
    int bxc = p & 3;         // column block 0..3
    int byb = p >> 2;        // row block 0..127
    if (rev) byb = 127 - byb;
    int m0 = byb * 64;
    int k0 = (bxc * 256 + threadIdx.x) * 8;
    if (threadIdx.x < 64) cs[threadIdx.x] = g_c[m0 + threadIdx.x];
    __syncthreads();
    float s[8] = {0.f, 0.f, 0.f, 0.f, 0.f, 0.f, 0.f, 0.f};
#pragma unroll 4
    for (int r = 0; r < 64; r++) {
        uint4 u = *(const uint4*)&g_Et[(size_t)(m0 + r) * KPROT + k0];
        float ev[8];
        h8_to_f(u, ev);
        float c = cs[r];
#pragma unroll
        for (int j = 0; j < 8; j++) s[j] = fmaf(ev[j], c, s[j]);
    }
#pragma unroll
    for (int j = 0; j < 8; j++) atomicAdd(&g_S[k0 + j], s[j]);
}

// ---------------- per-row loss finalize (uses row partials) -------------------------
__global__ void finalize_rows_kernel() {
    int m = blockIdx.x * blockDim.x + threadIdx.x;
    float tpt = 0.f, sptm = 0.f, mm = 0.f;
    if (m < MROWS) {
        float A = g_rowA[m], Bq = g_rowB[m], Dv = g_rowD[m];
        float Cv = g_rowC[m], F = g_rowF[m];
        float co = g_c[m];                    // c2
        float c3 = co / (co * A + SK_EPS);    // A == T3
        float lse_t = logf(Dv) + SHIFT;
        float lse_s = logf(F);
        tpt = c3 * (A * lse_t - Bq);
        mm = g_msk[m];
        sptm = mm * c3 * (A * lse_s - Cv * INV_ST);
    }
    tpt = blockSum(tpt);
    __syncthreads();
    sptm = blockSum(sptm);
    __syncthreads();
    mm = blockSum(mm);
    if (threadIdx.x == 0) {
        atomicAdd(&g_acc[0], tpt);
        atomicAdd(&g_acc[1], sptm);
        atomicAdd(&g_acc[2], mm);
    }
}

__global__ void koleo_kernel() {
    int k = blockIdx.x * blockDim.x + threadIdx.x;
    float term = 0.f;
    if (k < KPROT) {
        float g = __int_as_float(g_maxd[k]) - 2.0f;
        float d = sqrtf(fmaxf(2.f - 2.f * g, 0.f));
        term = logf(d + 1e-8f);
    }
    term = blockSum(term);
    if (threadIdx.x == 0) atomicAdd(&g_acc[3], term);
}

__global__ void finalize_kernel(float* __restrict__ out) {
    if (threadIdx.x == 0) {
        out[0] = g_acc[1] / fmaxf(g_acc[2], 1.f);
        out[1] = g_acc[0] * (1.f / (float)MROWS);
        out[2] = -g_acc[3] * (1.f / (float)KPROT);
    }
}

// ---------------- launch (single stream) ---------------------------------------------
extern "C" void kernel_launch(void* const* d_in, const int* in_sizes, int n_in,
                              void* d_out, int out_size) {
    int midx = -1;
    for (int i = 0; i < n_in; i++)
        if (in_sizes[i] == MROWS) { midx = i; break; }
    if (midx < 0) midx = 2;
    int others[3], no = 0;
    for (int i = 0; i < n_in && no < 3; i++)
        if (i != midx) others[no++] = i;

    const float* teacher = (const float*)d_in[others[0]];
    const float* student = (const float*)d_in[others[1]];
    const float* W       = (const float*)d_in[others[2]];
    const void*  mask    = d_in[midx];

    detect_mask_kernel<<<1, 256>>>((const unsigned char*)mask);
    build_mask_kernel<<<32, 256>>>(mask);
    init_kernel<<<32, 256>>>();

    norm_all_kernel<<<dim3(MROWS / 8, 3), 256>>>(teacher, student, W);

    // teacher GEMM -> Et + fused S1 colsum
    gemm_teacher_kernel<<<dim3(KPROT / 128, MROWS / 128), 256>>>();

    // Sinkhorn passes with interleaved koleo tiles (520 per launch):
    // S1 fused -> r1 ; T1 asc -> c1 ; S2 desc -> r2 ; T2 asc -> c2 ; S3 desc -> r3
    r_update_kernel<<<KPROT / 256, 256>>>();
    passT_koleo_kernel<<<8739, 256>>>(0, 0 * KCHUNK);
    passS_koleo_kernel<<<1040, 256>>>(1, 1 * KCHUNK);
    r_update_kernel<<<KPROT / 256, 256>>>();
    passT_koleo_kernel<<<8739, 256>>>(0, 2 * KCHUNK);
    passS_koleo_kernel<<<1040, 256>>>(1, 3 * KCHUNK);
    r_update_kernel<<<KPROT / 256, 256>>>();

    // student GEMM with fused loss epilogue (needs r3, c2, Et)
    gemm_student_kernel<<<dim3(KPROT / 128, MROWS / 128), 256>>>();

    finalize_rows_kernel<<<MROWS / 256, 256>>>();
    koleo_kernel<<<KPROT / 256, 256>>>();
    finalize_kernel<<<1, 32>>>((float*)d_out);
    (void)out_size;
}

// round 13
// speedup vs baseline: 1.0773x; 1.0773x over previous
#include <cuda_runtime.h>
#include <cuda_fp16.h>
#include <cstdint>

#define MROWS 8192   // B*N tokens
#define KPROT 8192   // prototypes
#define DDIM  768
#define INV_TT (1.0f/0.07f)
#define INV_ST 10.0f
#define SK_EPS 1e-8f
#define SHIFT  9.0f

// ---------------- scratch (static device globals; no allocation) -------------
static __device__ __align__(16) __half g_Et[(size_t)MROWS * KPROT]; // exp(Lt/tt - shift)
static __device__ __align__(16) __half g_th[MROWS * DDIM];
static __device__ __align__(16) __half g_sh[MROWS * DDIM];
static __device__ __align__(16) __half g_whr[KPROT * DDIM];
static __device__ __align__(16) __half g_whn[KPROT * DDIM];
static __device__ float  g_S[KPROT];
static __device__ float  g_r[KPROT];
static __device__ float  g_c[MROWS];
static __device__ float  g_msk[MROWS];
static __device__ int    g_maxd[KPROT];
// per-row loss partials (accumulated by student GEMM epilogue)
static __device__ float  g_rowA[MROWS];
static __device__ float  g_rowB[MROWS];
static __device__ float  g_rowD[MROWS];
static __device__ float  g_rowC[MROWS];
static __device__ float  g_rowF[MROWS];
static __device__ float  g_acc[4];
static __device__ int    g_maskmode;

// ---------------- reductions ---------------------------------------------------
__device__ __forceinline__ float warpSum(float v) {
#pragma unroll
    for (int o = 16; o > 0; o >>= 1) v += __shfl_down_sync(0xffffffffu, v, o);
    return v;
}
__device__ float blockSum(float v) {
    __shared__ float sb[32];
    int lane = threadIdx.x & 31, w = threadIdx.x >> 5;
    v = warpSum(v);
    __syncthreads();
    if (lane == 0) sb[w] = v;
    __syncthreads();
    int nw = (blockDim.x + 31) >> 5;
    v = (threadIdx.x < nw) ? sb[threadIdx.x] : 0.f;
    if (w == 0) v = warpSum(v);
    return v;
}

// ---------------- mask handling -------------------------------------------------
__global__ void detect_mask_kernel(const unsigned char* __restrict__ p) {
    __shared__ int c0, c1, c23;
    if (threadIdx.x == 0) { c0 = 0; c1 = 0; c23 = 0; }
    __syncthreads();
    int l0 = 0, l1 = 0, l23 = 0;
    for (int i = threadIdx.x; i < MROWS; i += blockDim.x) {
        unsigned char b = p[i];
        if (b) { int r = i & 3; if (r == 0) l0++; else if (r == 1) l1++; else l23++; }
    }
    atomicAdd(&c0, l0); atomicAdd(&c1, l1); atomicAdd(&c23, l23);
    __syncthreads();
    if (threadIdx.x == 0) {
        int mode;
        if (c1 == 0 && c23 == 0) mode = (c0 > 0) ? 1 : 0;
        else if (c1 == 0)        mode = 2;
        else                     mode = 0;
        g_maskmode = mode;
    }
}
__global__ void build_mask_kernel(const void* __restrict__ p) {
    int m = blockIdx.x * blockDim.x + threadIdx.x;
    if (m >= MROWS) return;
    int mode = g_maskmode;
    float v;
    if (mode == 1)      v = (((const int*)p)[m] != 0) ? 1.f : 0.f;
    else if (mode == 2) v = (((const float*)p)[m] != 0.f) ? 1.f : 0.f;
    else                v = (((const unsigned char*)p)[m] != 0) ? 1.f : 0.f;
    g_msk[m] = v;
}

__global__ void init_kernel() {
    int i = blockIdx.x * blockDim.x + threadIdx.x;
    if (i < KPROT) { g_S[i] = 0.f; g_r[i] = 1.f; g_maxd[i] = 0; }
    if (i < MROWS) {
        g_c[i] = 1.f;
        g_rowA[i] = 0.f; g_rowB[i] = 0.f; g_rowD[i] = 0.f;
        g_rowC[i] = 0.f; g_rowF[i] = 0.f;
    }
    if (i < 4) { g_acc[i] = 0.f; }
}

// ---------------- normalize: warp-per-row, 3 segments in one launch --------------
__global__ void __launch_bounds__(256)
norm_all_kernel(const float* __restrict__ t, const float* __restrict__ s,
                const float* __restrict__ w) {
    int wid = threadIdx.x >> 5, lane = threadIdx.x & 31;
    int row = blockIdx.x * 8 + wid;
    int seg = blockIdx.y;
    const float* in = (seg == 0) ? t : (seg == 1) ? s : w;
    __half* outN = (seg == 0) ? g_th : (seg == 1) ? g_sh : g_whn;
    const float4* x = (const float4*)(in + (size_t)row * DDIM);
    float4 v[6];
    float ss = 0.f;
#pragma unroll
    for (int i = 0; i < 6; i++) {
        v[i] = x[i * 32 + lane];
        ss += v[i].x * v[i].x + v[i].y * v[i].y + v[i].z * v[i].z + v[i].w * v[i].w;
    }
#pragma unroll
    for (int o = 16; o > 0; o >>= 1) ss += __shfl_xor_sync(0xffffffffu, ss, o);
    float inv = 1.f / fmaxf(sqrtf(ss), 1e-12f);
    uint2* oN = (uint2*)(outN + (size_t)row * DDIM);
#pragma unroll
    for (int i = 0; i < 6; i++) {
        __half2 h0 = __floats2half2_rn(v[i].x * inv, v[i].y * inv);
        __half2 h1 = __floats2half2_rn(v[i].z * inv, v[i].w * inv);
        uint2 u; u.x = *(uint32_t*)&h0; u.y = *(uint32_t*)&h1;
        oN[i * 32 + lane] = u;
    }
    if (seg == 2) {
        uint2* oR = (uint2*)(g_whr + (size_t)row * DDIM);
#pragma unroll
        for (int i = 0; i < 6; i++) {
            __half2 h0 = __floats2half2_rn(v[i].x, v[i].y);
            __half2 h1 = __floats2half2_rn(v[i].z, v[i].w);
            uint2 u; u.x = *(uint32_t*)&h0; u.y = *(uint32_t*)&h1;
            oR[i * 32 + lane] = u;
        }
    }
}

// ---------------- shared fp16 MMA mainloop ----------------------------------------
#define ROWB 80
#define TILEB (128 * ROWB)

__device__ __forceinline__ uint32_t smem_u32(const void* p) {
    uint32_t a;
    asm("{ .reg .u64 t; cvta.to.shared.u64 t, %1; cvt.u32.u64 %0, t; }" : "=r"(a) : "l"(p));
    return a;
}
__device__ __forceinline__ void ldsm_x4(uint32_t& r0, uint32_t& r1, uint32_t& r2, uint32_t& r3,
                                        uint32_t addr) {
    asm volatile("ldmatrix.sync.aligned.m8n8.x4.shared.b16 {%0,%1,%2,%3}, [%4];"
                 : "=r"(r0), "=r"(r1), "=r"(r2), "=r"(r3) : "r"(addr));
}
__device__ __forceinline__ void mma16816(float* c, uint32_t a0, uint32_t a1, uint32_t a2,
                                         uint32_t a3, uint32_t b0, uint32_t b1) {
    asm volatile("mma.sync.aligned.m16n8k16.row.col.f32.f16.f16.f32 "
                 "{%0,%1,%2,%3}, {%4,%5,%6,%7}, {%8,%9}, {%0,%1,%2,%3};"
                 : "+f"(c[0]), "+f"(c[1]), "+f"(c[2]), "+f"(c[3])
                 : "r"(a0), "r"(a1), "r"(a2), "r"(a3), "r"(b0), "r"(b1));
}
__device__ __forceinline__ void cpasync16(uint32_t dst, const void* src) {
    asm volatile("cp.async.cg.shared.global [%0], [%1], 16;" :: "r"(dst), "l"(src) : "memory");
}

__device__ __forceinline__ void run_mainloop(const __half* __restrict__ A,
                                             const __half* __restrict__ B,
                                             uint32_t sb, int m0, int n0,
                                             float acc[4][4][4]) {
    int tid = threadIdx.x, wid = tid >> 5, lane = tid & 31;
    int wm = (wid >> 2) * 64, wn = (wid & 3) * 32;
    uint32_t sA[2] = {sb, sb + TILEB};
    uint32_t sB[2] = {sb + 2 * TILEB, sb + 3 * TILEB};

#pragma unroll
    for (int i = 0; i < 4; i++)
#pragma unroll
        for (int j = 0; j < 4; j++)
#pragma unroll
            for (int q = 0; q < 4; q++) acc[i][j][q] = 0.f;

    const __half* gA = A + (size_t)m0 * DDIM;
    const __half* gB = B + (size_t)n0 * DDIM;
    int r0c = tid >> 2, q0c = tid & 3;
    int r1c = (tid + 256) >> 2, q1c = tid & 3;

    int aRow = wm + (lane & 15);
    int aColB = (lane >> 4) * 16;
    int bRow = wn + (lane & 7) + ((lane >> 4) << 3);
    int bColB = ((lane >> 3) & 1) * 16;

#define LOAD_TILE(buf, kt) do {                                               \
    int koff = (kt) * 32;                                                     \
    cpasync16(sA[buf] + r0c * ROWB + q0c * 16, gA + (size_t)r0c * DDIM + koff + q0c * 8); \
    cpasync16(sB[buf] + r0c * ROWB + q0c * 16, gB + (size_t)r0c * DDIM + koff + q0c * 8); \
    cpasync16(sA[buf] + r1c * ROWB + q1c * 16, gA + (size_t)r1c * DDIM + koff + q1c * 8); \
    cpasync16(sB[buf] + r1c * ROWB + q1c * 16, gB + (size_t)r1c * DDIM + koff + q1c * 8); \
    asm volatile("cp.async.commit_group;" ::: "memory");                      \
} while (0)

    LOAD_TILE(0, 0);
    const int NKT = DDIM / 32;
#pragma unroll 1
    for (int kt = 0; kt < NKT; kt++) {
        int buf = kt & 1;
        if (kt + 1 < NKT) {
            LOAD_TILE(buf ^ 1, kt + 1);
            asm volatile("cp.async.wait_group 1;" ::: "memory");
        } else {
            asm volatile("cp.async.wait_group 0;" ::: "memory");
        }
        __syncthreads();
#pragma unroll
        for (int ks = 0; ks < 2; ks++) {
            uint32_t a[4][4], b[2][4];
#pragma unroll
            for (int mi = 0; mi < 4; mi++)
                ldsm_x4(a[mi][0], a[mi][1], a[mi][2], a[mi][3],
                        sA[buf] + (uint32_t)((aRow + mi * 16) * ROWB + ks * 32 + aColB));
#pragma unroll
            for (int np = 0; np < 2; np++)
                ldsm_x4(b[np][0], b[np][1], b[np][2], b[np][3],
                        sB[buf] + (uint32_t)((bRow + np * 16) * ROWB + ks * 32 + bColB));
#pragma unroll
            for (int mi = 0; mi < 4; mi++)
#pragma unroll
                for (int ni = 0; ni < 4; ni++) {
                    int np = ni >> 1, sel = (ni & 1) * 2;
                    mma16816(acc[mi][ni], a[mi][0], a[mi][1], a[mi][2], a[mi][3],
                             b[np][sel], b[np][sel + 1]);
                }
        }
        __syncthreads();
    }
#undef LOAD_TILE
}

// ---------------- GEMM0: teacher -> g_Et + fused S1 colsum -------------------------
__global__ void __launch_bounds__(256, 2)
gemm_teacher_kernel() {
    __shared__ __align__(16) uint8_t smem[4 * TILEB];
    int tid = threadIdx.x, wid = tid >> 5, lane = tid & 31;
    int m0 = blockIdx.y * 128, n0 = blockIdx.x * 128;
    int wm = (wid >> 2) * 64, wn = (wid & 3) * 32;
    float acc[4][4][4];
    run_mainloop(g_th, g_whr, smem_u32(smem), m0, n0, acc);

    int tr = lane >> 2, tc = (lane & 3) * 2;
#pragma unroll
    for (int mi = 0; mi < 4; mi++) {
        int gr0 = m0 + wm + mi * 16 + tr;
#pragma unroll
        for (int ni = 0; ni < 4; ni++) {
            int gc = n0 + wn + ni * 8 + tc;
            float e0 = __expf(acc[mi][ni][0] * INV_TT - SHIFT);
            float e1 = __expf(acc[mi][ni][1] * INV_TT - SHIFT);
            float e2 = __expf(acc[mi][ni][2] * INV_TT - SHIFT);
            float e3 = __expf(acc[mi][ni][3] * INV_TT - SHIFT);
            *(__half2*)&g_Et[(size_t)gr0 * KPROT + gc] = __floats2half2_rn(e0, e1);
            *(__half2*)&g_Et[(size_t)(gr0 + 8) * KPROT + gc] = __floats2half2_rn(e2, e3);
            acc[mi][ni][0] = e0; acc[mi][ni][1] = e1;
            acc[mi][ni][2] = e2; acc[mi][ni][3] = e3;
        }
    }
#pragma unroll
    for (int ni = 0; ni < 4; ni++) {
        float s0 = 0.f, s1 = 0.f;
#pragma unroll
        for (int mi = 0; mi < 4; mi++) {
            s0 += acc[mi][ni][0] + acc[mi][ni][2];
            s1 += acc[mi][ni][1] + acc[mi][ni][3];
        }
#pragma unroll
        for (int o = 4; o < 32; o <<= 1) {
            s0 += __shfl_down_sync(0xffffffffu, s0, o);
            s1 += __shfl_down_sync(0xffffffffu, s1, o);
        }
        if (lane < 4) {
            int gc = n0 + wn + ni * 8 + lane * 2;
            atomicAdd(&g_S[gc], s0);
            atomicAdd(&g_S[gc + 1], s1);
        }
    }
}

// ---------------- launch 2: z=0 student GEMM + fused loss ; z=1 koleo --------------
// Student y-mapping reversed: first wave reads high Et rows (hot after S3 asc).
__global__ void __launch_bounds__(256, 2)
gemm_sk_kernel() {
    const int mode = blockIdx.z;
    if (mode == 1 && blockIdx.x > blockIdx.y) return;  // koleo: lower triangle only

    __shared__ __align__(16) uint8_t smem[4 * TILEB];
    int tid = threadIdx.x, wid = tid >> 5, lane = tid & 31;
    int by = (mode == 0) ? (MROWS / 128 - 1 - blockIdx.y) : blockIdx.y;
    int m0 = by * 128, n0 = blockIdx.x * 128;
    int wm = (wid >> 2) * 64, wn = (wid & 3) * 32;
    float acc[4][4][4];
    run_mainloop((mode == 0) ? g_sh : g_whn, (mode == 0) ? g_whr : g_whn,
                 smem_u32(smem), m0, n0, acc);

    int tr = lane >> 2, tc = (lane & 3) * 2;

    if (mode == 0) {
        // fused loss epilogue: per-row partial sums A,Bq,Dv,Cv,F (r3 and Et ready)
#pragma unroll
        for (int mi = 0; mi < 4; mi++) {
            int gr0 = m0 + wm + mi * 16 + tr;
            int gr1 = gr0 + 8;
            float A0 = 0.f, B0 = 0.f, D0 = 0.f, C0 = 0.f, F0 = 0.f;
            float A1 = 0.f, B1 = 0.f, D1 = 0.f, C1 = 0.f, F1 = 0.f;
#pragma unroll
            for (int ni = 0; ni < 4; ni++) {
                int gc = n0 + wn + ni * 8 + tc;
                float2 rr = *(const float2*)&g_r[gc];
                float2 f01 = __half22float2(*(const __half2*)&g_Et[(size_t)gr0 * KPROT + gc]);
                float2 f23 = __half22float2(*(const __half2*)&g_Et[(size_t)gr1 * KPROT + gc]);
                {
                    float e0 = f01.x, e1 = f01.y;
                    float er0 = e0 * rr.x, er1 = e1 * rr.y;
                    float lq0 = __logf(fmaxf(e0, 6e-8f)) + SHIFT;
                    float lq1 = __logf(fmaxf(e1, 6e-8f)) + SHIFT;
                    float ls0 = acc[mi][ni][0], ls1 = acc[mi][ni][1];
                    A0 += er0 + er1;
                    B0 = fmaf(er0, lq0, fmaf(er1, lq1, B0));
                    D0 += e0 + e1;
                    C0 = fmaf(er0, ls0, fmaf(er1, ls1, C0));
                    F0 += __expf(ls0 * INV_ST) + __expf(ls1 * INV_ST);
                }
                {
                    float e0 = f23.x, e1 = f23.y;
                    float er0 = e0 * rr.x, er1 = e1 * rr.y;
                    float lq0 = __logf(fmaxf(e0, 6e-8f)) + SHIFT;
                    float lq1 = __logf(fmaxf(e1, 6e-8f)) + SHIFT;
                    float ls0 = acc[mi][ni][2], ls1 = acc[mi][ni][3];
                    A1 += er0 + er1;
                    B1 = fmaf(er0, lq0, fmaf(er1, lq1, B1));
                    D1 += e0 + e1;
                    C1 = fmaf(er0, ls0, fmaf(er1, ls1, C1));
                    F1 += __expf(ls0 * INV_ST) + __expf(ls1 * INV_ST);
                }
            }
#define QRED(x) do { x += __shfl_xor_sync(0xffffffffu, x, 1); \
                     x += __shfl_xor_sync(0xffffffffu, x, 2); } while (0)
            QRED(A0); QRED(B0); QRED(D0); QRED(C0); QRED(F0);
            QRED(A1); QRED(B1); QRED(D1); QRED(C1); QRED(F1);
#undef QRED
            if ((lane & 3) == 0) {
                atomicAdd(&g_rowA[gr0], A0); atomicAdd(&g_rowB[gr0], B0);
                atomicAdd(&g_rowD[gr0], D0); atomicAdd(&g_rowC[gr0], C0);
                atomicAdd(&g_rowF[gr0], F0);
                atomicAdd(&g_rowA[gr1], A1); atomicAdd(&g_rowB[gr1], B1);
                atomicAdd(&g_rowD[gr1], D1); atomicAdd(&g_rowC[gr1], C1);
                atomicAdd(&g_rowF[gr1], F1);
            }
        }
    } else {
        float cm[4][2];
#pragma unroll
        for (int ni = 0; ni < 4; ni++) { cm[ni][0] = -2.f; cm[ni][1] = -2.f; }
#pragma unroll
        for (int mi = 0; mi < 4; mi++) {
            int gr0 = m0 + wm + mi * 16 + tr;
            int gr1 = gr0 + 8;
            float mx0 = -2.f, mx1 = -2.f;
#pragma unroll
            for (int ni = 0; ni < 4; ni++) {
                int gc = n0 + wn + ni * 8 + tc;
                float v0 = (gc == gr0) ? -2.f : acc[mi][ni][0];
                float v1 = (gc + 1 == gr0) ? -2.f : acc[mi][ni][1];
                float v2 = (gc == gr1) ? -2.f : acc[mi][ni][2];
                float v3 = (gc + 1 == gr1) ? -2.f : acc[mi][ni][3];
                mx0 = fmaxf(mx0, fmaxf(v0, v1));
                mx1 = fmaxf(mx1, fmaxf(v2, v3));
                cm[ni][0] = fmaxf(cm[ni][0], fmaxf(v0, v2));
                cm[ni][1] = fmaxf(cm[ni][1], fmaxf(v1, v3));
            }
#pragma unroll
            for (int o = 1; o < 4; o <<= 1) {
                mx0 = fmaxf(mx0, __shfl_xor_sync(0xffffffffu, mx0, o));
                mx1 = fmaxf(mx1, __shfl_xor_sync(0xffffffffu, mx1, o));
            }
            if ((lane & 3) == 0) {
                atomicMax(&g_maxd[gr0], __float_as_int(mx0 + 2.0f));
                atomicMax(&g_maxd[gr1], __float_as_int(mx1 + 2.0f));
            }
        }
#pragma unroll
        for (int ni = 0; ni < 4; ni++) {
            float c0 = cm[ni][0], c1 = cm[ni][1];
#pragma unroll
            for (int o = 4; o < 32; o <<= 1) {
                c0 = fmaxf(c0, __shfl_xor_sync(0xffffffffu, c0, o));
                c1 = fmaxf(c1, __shfl_xor_sync(0xffffffffu, c1, o));
            }
            if (lane < 4) {
                int gc = n0 + wn + ni * 8 + lane * 2;
                atomicMax(&g_maxd[gc], __float_as_int(c0 + 2.0f));
                atomicMax(&g_maxd[gc + 1], __float_as_int(c1 + 2.0f));
            }
        }
    }
}

// ---------------- helpers --------------------------------------------------------
__device__ __forceinline__ void h8_to_f(const uint4& u, float f[8]) {
    __half2 a = *(const __half2*)&u.x, b = *(const __half2*)&u.y;
    __half2 c = *(const __half2*)&u.z, d = *(const __half2*)&u.w;
    float2 fa = __half22float2(a), fb = __half22float2(b);
    float2 fc = __half22float2(c), fd = __half22float2(d);
    f[0] = fa.x; f[1] = fa.y; f[2] = fb.x; f[3] = fb.y;
    f[4] = fc.x; f[5] = fc.y; f[6] = fd.x; f[7] = fd.y;
}

// ---------------- Sinkhorn passes (L2-aligned direction alternation) ----------------
__global__ void r_update_kernel() {
    int k = blockIdx.x * blockDim.x + threadIdx.x;
    if (k < KPROT) {
        float r = g_r[k], s = g_S[k];
        g_r[k] = r / (r * s + SK_EPS);
        g_S[k] = 0.f;
    }
}

__global__ void pass_T_kernel(int rev) {
    int m = rev ? (MROWS - 1 - blockIdx.x) : blockIdx.x;
    const uint4* row = (const uint4*)(g_Et + (size_t)m * KPROT);
    float t = 0.f;
    for (int i = threadIdx.x; i < KPROT / 8; i += blockDim.x) {
        uint4 u = row[i];
        float ev[8];
        h8_to_f(u, ev);
        float4 r0 = *(const float4*)(g_r + i * 8);
        float4 r1 = *(const float4*)(g_r + i * 8 + 4);
        t += ev[0] * r0.x + ev[1] * r0.y + ev[2] * r0.z + ev[3] * r0.w
           + ev[4] * r1.x + ev[5] * r1.y + ev[6] * r1.z + ev[7] * r1.w;
    }
    t = blockSum(t);
    if (threadIdx.x == 0) {
        float co = g_c[m];
        g_c[m] = co / (co * t + SK_EPS);
    }
}

__global__ void pass_S_kernel(int rev) {
    int yb = rev ? (gridDim.y - 1 - blockIdx.y) : blockIdx.y;
    int m0 = yb * 64;
    int k0 = (blockIdx.x * 256 + threadIdx.x) * 8;
    __shared__ float cs[64];
    if (threadIdx.x < 64) cs[threadIdx.x] = g_c[m0 + threadIdx.x];
    __syncthreads();
    float s[8] = {0.f, 0.f, 0.f, 0.f, 0.f, 0.f, 0.f, 0.f};
#pragma unroll 4
    for (int r = 0; r < 64; r++) {
        uint4 u = *(const uint4*)&g_Et[(size_t)(m0 + r) * KPROT + k0];
        float ev[8];
        h8_to_f(u, ev);
        float c = cs[r];
#pragma unroll
        for (int j = 0; j < 8; j++) s[j] = fmaf(ev[j], c, s[j]);
    }
#pragma unroll
    for (int j = 0; j < 8; j++) atomicAdd(&g_S[k0 + j], s[j]);
}

// ---------------- per-row loss finalize (uses row partials) -------------------------
__global__ void finalize_rows_kernel() {
    int m = blockIdx.x * blockDim.x + threadIdx.x;
    float tpt = 0.f, sptm = 0.f, mm = 0.f;
    if (m < MROWS) {
        float A = g_rowA[m], Bq = g_rowB[m], Dv = g_rowD[m];
        float Cv = g_rowC[m], F = g_rowF[m];
        float co = g_c[m];                    // c2
        float c3 = co / (co * A + SK_EPS);    // A == T3
        float lse_t = logf(Dv) + SHIFT;
        float lse_s = logf(F);
        tpt = c3 * (A * lse_t - Bq);
        mm = g_msk[m];
        sptm = mm * c3 * (A * lse_s - Cv * INV_ST);
    }
    tpt = blockSum(tpt);
    __syncthreads();
    sptm = blockSum(sptm);
    __syncthreads();
    mm = blockSum(mm);
    if (threadIdx.x == 0) {
        atomicAdd(&g_acc[0], tpt);
        atomicAdd(&g_acc[1], sptm);
        atomicAdd(&g_acc[2], mm);
    }
}

__global__ void koleo_kernel() {
    int k = blockIdx.x * blockDim.x + threadIdx.x;
    float term = 0.f;
    if (k < KPROT) {
        float g = __int_as_float(g_maxd[k]) - 2.0f;
        float d = sqrtf(fmaxf(2.f - 2.f * g, 0.f));
        term = logf(d + 1e-8f);
    }
    term = blockSum(term);
    if (threadIdx.x == 0) atomicAdd(&g_acc[3], term);
}

__global__ void finalize_kernel(float* __restrict__ out) {
    if (threadIdx.x == 0) {
        out[0] = g_acc[1] / fmaxf(g_acc[2], 1.f);
        out[1] = g_acc[0] * (1.f / (float)MROWS);
        out[2] = -g_acc[3] * (1.f / (float)KPROT);
    }
}

// ---------------- launch (single stream) ---------------------------------------------
extern "C" void kernel_launch(void* const* d_in, const int* in_sizes, int n_in,
                              void* d_out, int out_size) {
    int midx = -1;
    for (int i = 0; i < n_in; i++)
        if (in_sizes[i] == MROWS) { midx = i; break; }
    if (midx < 0) midx = 2;
    int others[3], no = 0;
    for (int i = 0; i < n_in && no < 3; i++)
        if (i != midx) others[no++] = i;

    const float* teacher = (const float*)d_in[others[0]];
    const float* student = (const float*)d_in[others[1]];
    const float* W       = (const float*)d_in[others[2]];
    const void*  mask    = d_in[midx];

    detect_mask_kernel<<<1, 256>>>((const unsigned char*)mask);
    build_mask_kernel<<<32, 256>>>(mask);
    init_kernel<<<32, 256>>>();

    norm_all_kernel<<<dim3(MROWS / 8, 3), 256>>>(teacher, student, W);

    // teacher GEMM -> Et + fused S1 colsum (writes ascending row-blocks, ends HIGH)
    gemm_teacher_kernel<<<dim3(KPROT / 128, MROWS / 128), 256>>>();

    // Sinkhorn, L2-aligned chain:
    // GEMM ends high -> T1 DESC -> ends low -> S2 ASC -> ends high ->
    // T2 DESC -> ends low -> S3 ASC -> ends high -> student GEMM (y-reversed)
    r_update_kernel<<<KPROT / 256, 256>>>();
    pass_T_kernel<<<MROWS, 256>>>(1);
    pass_S_kernel<<<dim3(KPROT / 2048, MROWS / 64), 256>>>(0);
    r_update_kernel<<<KPROT / 256, 256>>>();
    pass_T_kernel<<<MROWS, 256>>>(1);
    pass_S_kernel<<<dim3(KPROT / 2048, MROWS / 64), 256>>>(0);
    r_update_kernel<<<KPROT / 256, 256>>>();

    // student GEMM with fused loss epilogue (needs r3, c2, Et) + koleo GEMM
    gemm_sk_kernel<<<dim3(KPROT / 128, MROWS / 128, 2), 256>>>();

    finalize_rows_kernel<<<MROWS / 256, 256>>>();
    koleo_kernel<<<KPROT / 256, 256>>>();
    finalize_kernel<<<1, 32>>>((float*)d_out);
    (void)out_size;
}

// round 14
// speedup vs baseline: 1.1263x; 1.0455x over previous
#include <cuda_runtime.h>
#include <cuda_fp16.h>
#include <cstdint>

#define MROWS 8192   // B*N tokens
#define KPROT 8192   // prototypes
#define DDIM  768
#define INV_TT (1.0f/0.07f)
#define INV_ST 10.0f
#define SK_EPS 1e-8f
#define SHIFT  9.0f

// ---------------- scratch (static device globals; no allocation) -------------
static __device__ __align__(16) __half g_Et[(size_t)MROWS * KPROT]; // exp(Lt/tt - shift)
static __device__ __align__(16) __half g_th[MROWS * DDIM];
static __device__ __align__(16) __half g_sh[MROWS * DDIM];
static __device__ __align__(16) __half g_whr[KPROT * DDIM];
static __device__ __align__(16) __half g_whn[KPROT * DDIM];
static __device__ float  g_S[KPROT];
static __device__ float  g_r[KPROT];
static __device__ float  g_c[MROWS];
static __device__ float  g_msk[MROWS];
static __device__ int    g_maxd[KPROT];
// per-row loss partials (accumulated by student GEMM epilogue)
static __device__ float  g_rowA[MROWS];
static __device__ float  g_rowB[MROWS];
static __device__ float  g_rowD[MROWS];
static __device__ float  g_rowC[MROWS];
static __device__ float  g_rowF[MROWS];
static __device__ float  g_acc[4];
static __device__ int    g_maskmode;

// ---------------- reductions ---------------------------------------------------
__device__ __forceinline__ float warpSum(float v) {
#pragma unroll
    for (int o = 16; o > 0; o >>= 1) v += __shfl_down_sync(0xffffffffu, v, o);
    return v;
}
__device__ float blockSum(float v) {
    __shared__ float sb[32];
    int lane = threadIdx.x & 31, w = threadIdx.x >> 5;
    v = warpSum(v);
    __syncthreads();
    if (lane == 0) sb[w] = v;
    __syncthreads();
    int nw = (blockDim.x + 31) >> 5;
    v = (threadIdx.x < nw) ? sb[threadIdx.x] : 0.f;
    if (w == 0) v = warpSum(v);
    return v;
}

// ---------------- mask handling -------------------------------------------------
__global__ void detect_mask_kernel(const unsigned char* __restrict__ p) {
    __shared__ int c0, c1, c23;
    if (threadIdx.x == 0) { c0 = 0; c1 = 0; c23 = 0; }
    __syncthreads();
    int l0 = 0, l1 = 0, l23 = 0;
    for (int i = threadIdx.x; i < MROWS; i += blockDim.x) {
        unsigned char b = p[i];
        if (b) { int r = i & 3; if (r == 0) l0++; else if (r == 1) l1++; else l23++; }
    }
    atomicAdd(&c0, l0); atomicAdd(&c1, l1); atomicAdd(&c23, l23);
    __syncthreads();
    if (threadIdx.x == 0) {
        int mode;
        if (c1 == 0 && c23 == 0) mode = (c0 > 0) ? 1 : 0;
        else if (c1 == 0)        mode = 2;
        else                     mode = 0;
        g_maskmode = mode;
    }
}
__global__ void build_mask_kernel(const void* __restrict__ p) {
    int m = blockIdx.x * blockDim.x + threadIdx.x;
    if (m >= MROWS) return;
    int mode = g_maskmode;
    float v;
    if (mode == 1)      v = (((const int*)p)[m] != 0) ? 1.f : 0.f;
    else if (mode == 2) v = (((const float*)p)[m] != 0.f) ? 1.f : 0.f;
    else                v = (((const unsigned char*)p)[m] != 0) ? 1.f : 0.f;
    g_msk[m] = v;
}

__global__ void init_kernel() {
    int i = blockIdx.x * blockDim.x + threadIdx.x;
    if (i < KPROT) { g_S[i] = 0.f; g_r[i] = 1.f; g_maxd[i] = 0; }
    if (i < MROWS) {
        g_c[i] = 1.f;
        g_rowA[i] = 0.f; g_rowB[i] = 0.f; g_rowD[i] = 0.f;
        g_rowC[i] = 0.f; g_rowF[i] = 0.f;
    }
    if (i < 4) { g_acc[i] = 0.f; }
}

// ---------------- normalize: warp-per-row, 3 segments in one launch --------------
__global__ void __launch_bounds__(256)
norm_all_kernel(const float* __restrict__ t, const float* __restrict__ s,
                const float* __restrict__ w) {
    int wid = threadIdx.x >> 5, lane = threadIdx.x & 31;
    int row = blockIdx.x * 8 + wid;
    int seg = blockIdx.y;
    const float* in = (seg == 0) ? t : (seg == 1) ? s : w;
    __half* outN = (seg == 0) ? g_th : (seg == 1) ? g_sh : g_whn;
    const float4* x = (const float4*)(in + (size_t)row * DDIM);
    float4 v[6];
    float ss = 0.f;
#pragma unroll
    for (int i = 0; i < 6; i++) {
        v[i] = x[i * 32 + lane];
        ss += v[i].x * v[i].x + v[i].y * v[i].y + v[i].z * v[i].z + v[i].w * v[i].w;
    }
#pragma unroll
    for (int o = 16; o > 0; o >>= 1) ss += __shfl_xor_sync(0xffffffffu, ss, o);
    float inv = 1.f / fmaxf(sqrtf(ss), 1e-12f);
    uint2* oN = (uint2*)(outN + (size_t)row * DDIM);
#pragma unroll
    for (int i = 0; i < 6; i++) {
        __half2 h0 = __floats2half2_rn(v[i].x * inv, v[i].y * inv);
        __half2 h1 = __floats2half2_rn(v[i].z * inv, v[i].w * inv);
        uint2 u; u.x = *(uint32_t*)&h0; u.y = *(uint32_t*)&h1;
        oN[i * 32 + lane] = u;
    }
    if (seg == 2) {
        uint2* oR = (uint2*)(g_whr + (size_t)row * DDIM);
#pragma unroll
        for (int i = 0; i < 6; i++) {
            __half2 h0 = __floats2half2_rn(v[i].x, v[i].y);
            __half2 h1 = __floats2half2_rn(v[i].z, v[i].w);
            uint2 u; u.x = *(uint32_t*)&h0; u.y = *(uint32_t*)&h1;
            oR[i * 32 + lane] = u;
        }
    }
}

// ---------------- shared fp16 MMA mainloop ----------------------------------------
#define ROWB 80
#define TILEB (128 * ROWB)

__device__ __forceinline__ uint32_t smem_u32(const void* p) {
    uint32_t a;
    asm("{ .reg .u64 t; cvta.to.shared.u64 t, %1; cvt.u32.u64 %0, t; }" : "=r"(a) : "l"(p));
    return a;
}
__device__ __forceinline__ void ldsm_x4(uint32_t& r0, uint32_t& r1, uint32_t& r2, uint32_t& r3,
                                        uint32_t addr) {
    asm volatile("ldmatrix.sync.aligned.m8n8.x4.shared.b16 {%0,%1,%2,%3}, [%4];"
                 : "=r"(r0), "=r"(r1), "=r"(r2), "=r"(r3) : "r"(addr));
}
__device__ __forceinline__ void mma16816(float* c, uint32_t a0, uint32_t a1, uint32_t a2,
                                         uint32_t a3, uint32_t b0, uint32_t b1) {
    asm volatile("mma.sync.aligned.m16n8k16.row.col.f32.f16.f16.f32 "
                 "{%0,%1,%2,%3}, {%4,%5,%6,%7}, {%8,%9}, {%0,%1,%2,%3};"
                 : "+f"(c[0]), "+f"(c[1]), "+f"(c[2]), "+f"(c[3])
                 : "r"(a0), "r"(a1), "r"(a2), "r"(a3), "r"(b0), "r"(b1));
}
__device__ __forceinline__ void cpasync16(uint32_t dst, const void* src) {
    asm volatile("cp.async.cg.shared.global [%0], [%1], 16;" :: "r"(dst), "l"(src) : "memory");
}

__device__ __forceinline__ void run_mainloop(const __half* __restrict__ A,
                                             const __half* __restrict__ B,
                                             uint32_t sb, int m0, int n0,
                                             float acc[4][4][4]) {
    int tid = threadIdx.x, wid = tid >> 5, lane = tid & 31;
    int wm = (wid >> 2) * 64, wn = (wid & 3) * 32;
    uint32_t sA[2] = {sb, sb + TILEB};
    uint32_t sB[2] = {sb + 2 * TILEB, sb + 3 * TILEB};

#pragma unroll
    for (int i = 0; i < 4; i++)
#pragma unroll
        for (int j = 0; j < 4; j++)
#pragma unroll
            for (int q = 0; q < 4; q++) acc[i][j][q] = 0.f;

    const __half* gA = A + (size_t)m0 * DDIM;
    const __half* gB = B + (size_t)n0 * DDIM;
    int r0c = tid >> 2, q0c = tid & 3;
    int r1c = (tid + 256) >> 2, q1c = tid & 3;

    int aRow = wm + (lane & 15);
    int aColB = (lane >> 4) * 16;
    int bRow = wn + (lane & 7) + ((lane >> 4) << 3);
    int bColB = ((lane >> 3) & 1) * 16;

#define LOAD_TILE(buf, kt) do {                                               \
    int koff = (kt) * 32;                                                     \
    cpasync16(sA[buf] + r0c * ROWB + q0c * 16, gA + (size_t)r0c * DDIM + koff + q0c * 8); \
    cpasync16(sB[buf] + r0c * ROWB + q0c * 16, gB + (size_t)r0c * DDIM + koff + q0c * 8); \
    cpasync16(sA[buf] + r1c * ROWB + q1c * 16, gA + (size_t)r1c * DDIM + koff + q1c * 8); \
    cpasync16(sB[buf] + r1c * ROWB + q1c * 16, gB + (size_t)r1c * DDIM + koff + q1c * 8); \
    asm volatile("cp.async.commit_group;" ::: "memory");                      \
} while (0)

    LOAD_TILE(0, 0);
    const int NKT = DDIM / 32;
#pragma unroll 1
    for (int kt = 0; kt < NKT; kt++) {
        int buf = kt & 1;
        if (kt + 1 < NKT) {
            LOAD_TILE(buf ^ 1, kt + 1);
            asm volatile("cp.async.wait_group 1;" ::: "memory");
        } else {
            asm volatile("cp.async.wait_group 0;" ::: "memory");
        }
        __syncthreads();
#pragma unroll
        for (int ks = 0; ks < 2; ks++) {
            uint32_t a[4][4], b[2][4];
#pragma unroll
            for (int mi = 0; mi < 4; mi++)
                ldsm_x4(a[mi][0], a[mi][1], a[mi][2], a[mi][3],
                        sA[buf] + (uint32_t)((aRow + mi * 16) * ROWB + ks * 32 + aColB));
#pragma unroll
            for (int np = 0; np < 2; np++)
                ldsm_x4(b[np][0], b[np][1], b[np][2], b[np][3],
                        sB[buf] + (uint32_t)((bRow + np * 16) * ROWB + ks * 32 + bColB));
#pragma unroll
            for (int mi = 0; mi < 4; mi++)
#pragma unroll
                for (int ni = 0; ni < 4; ni++) {
                    int np = ni >> 1, sel = (ni & 1) * 2;
                    mma16816(acc[mi][ni], a[mi][0], a[mi][1], a[mi][2], a[mi][3],
                             b[np][sel], b[np][sel + 1]);
                }
        }
        __syncthreads();
    }
#undef LOAD_TILE
}

// ---------------- GEMM0: teacher -> g_Et + fused S1 colsum -------------------------
__global__ void __launch_bounds__(256, 2)
gemm_teacher_kernel() {
    __shared__ __align__(16) uint8_t smem[4 * TILEB];
    int tid = threadIdx.x, wid = tid >> 5, lane = tid & 31;
    int m0 = blockIdx.y * 128, n0 = blockIdx.x * 128;
    int wm = (wid >> 2) * 64, wn = (wid & 3) * 32;
    float acc[4][4][4];
    run_mainloop(g_th, g_whr, smem_u32(smem), m0, n0, acc);

    int tr = lane >> 2, tc = (lane & 3) * 2;
#pragma unroll
    for (int mi = 0; mi < 4; mi++) {
        int gr0 = m0 + wm + mi * 16 + tr;
#pragma unroll
        for (int ni = 0; ni < 4; ni++) {
            int gc = n0 + wn + ni * 8 + tc;
            float e0 = __expf(acc[mi][ni][0] * INV_TT - SHIFT);
            float e1 = __expf(acc[mi][ni][1] * INV_TT - SHIFT);
            float e2 = __expf(acc[mi][ni][2] * INV_TT - SHIFT);
            float e3 = __expf(acc[mi][ni][3] * INV_TT - SHIFT);
            *(__half2*)&g_Et[(size_t)gr0 * KPROT + gc] = __floats2half2_rn(e0, e1);
            *(__half2*)&g_Et[(size_t)(gr0 + 8) * KPROT + gc] = __floats2half2_rn(e2, e3);
            acc[mi][ni][0] = e0; acc[mi][ni][1] = e1;
            acc[mi][ni][2] = e2; acc[mi][ni][3] = e3;
        }
    }
#pragma unroll
    for (int ni = 0; ni < 4; ni++) {
        float s0 = 0.f, s1 = 0.f;
#pragma unroll
        for (int mi = 0; mi < 4; mi++) {
            s0 += acc[mi][ni][0] + acc[mi][ni][2];
            s1 += acc[mi][ni][1] + acc[mi][ni][3];
        }
#pragma unroll
        for (int o = 4; o < 32; o <<= 1) {
            s0 += __shfl_down_sync(0xffffffffu, s0, o);
            s1 += __shfl_down_sync(0xffffffffu, s1, o);
        }
        if (lane < 4) {
            int gc = n0 + wn + ni * 8 + lane * 2;
            atomicAdd(&g_S[gc], s0);
            atomicAdd(&g_S[gc + 1], s1);
        }
    }
}

// ---------------- launch 2: z=0 student GEMM + fused loss ; z=1 koleo --------------
// Student y-mapping reversed: first wave reads high Et rows (hot after pass B asc).
__global__ void __launch_bounds__(256, 2)
gemm_sk_kernel() {
    const int mode = blockIdx.z;
    if (mode == 1 && blockIdx.x > blockIdx.y) return;  // koleo: lower triangle only

    __shared__ __align__(16) uint8_t smem[4 * TILEB];
    int tid = threadIdx.x, wid = tid >> 5, lane = tid & 31;
    int by = (mode == 0) ? (MROWS / 128 - 1 - blockIdx.y) : blockIdx.y;
    int m0 = by * 128, n0 = blockIdx.x * 128;
    int wm = (wid >> 2) * 64, wn = (wid & 3) * 32;
    float acc[4][4][4];
    run_mainloop((mode == 0) ? g_sh : g_whn, (mode == 0) ? g_whr : g_whn,
                 smem_u32(smem), m0, n0, acc);

    int tr = lane >> 2, tc = (lane & 3) * 2;

    if (mode == 0) {
        // fused loss epilogue: per-row partial sums A,Bq,Dv,Cv,F (r3 and Et ready)
#pragma unroll
        for (int mi = 0; mi < 4; mi++) {
            int gr0 = m0 + wm + mi * 16 + tr;
            int gr1 = gr0 + 8;
            float A0 = 0.f, B0 = 0.f, D0 = 0.f, C0 = 0.f, F0 = 0.f;
            float A1 = 0.f, B1 = 0.f, D1 = 0.f, C1 = 0.f, F1 = 0.f;
#pragma unroll
            for (int ni = 0; ni < 4; ni++) {
                int gc = n0 + wn + ni * 8 + tc;
                float2 rr = *(const float2*)&g_r[gc];
                float2 f01 = __half22float2(*(const __half2*)&g_Et[(size_t)gr0 * KPROT + gc]);
                float2 f23 = __half22float2(*(const __half2*)&g_Et[(size_t)gr1 * KPROT + gc]);
                {
                    float e0 = f01.x, e1 = f01.y;
                    float er0 = e0 * rr.x, er1 = e1 * rr.y;
                    float lq0 = __logf(fmaxf(e0, 6e-8f)) + SHIFT;
                    float lq1 = __logf(fmaxf(e1, 6e-8f)) + SHIFT;
                    float ls0 = acc[mi][ni][0], ls1 = acc[mi][ni][1];
                    A0 += er0 + er1;
                    B0 = fmaf(er0, lq0, fmaf(er1, lq1, B0));
                    D0 += e0 + e1;
                    C0 = fmaf(er0, ls0, fmaf(er1, ls1, C0));
                    F0 += __expf(ls0 * INV_ST) + __expf(ls1 * INV_ST);
                }
                {
                    float e0 = f23.x, e1 = f23.y;
                    float er0 = e0 * rr.x, er1 = e1 * rr.y;
                    float lq0 = __logf(fmaxf(e0, 6e-8f)) + SHIFT;
                    float lq1 = __logf(fmaxf(e1, 6e-8f)) + SHIFT;
                    float ls0 = acc[mi][ni][2], ls1 = acc[mi][ni][3];
                    A1 += er0 + er1;
                    B1 = fmaf(er0, lq0, fmaf(er1, lq1, B1));
                    D1 += e0 + e1;
                    C1 = fmaf(er0, ls0, fmaf(er1, ls1, C1));
                    F1 += __expf(ls0 * INV_ST) + __expf(ls1 * INV_ST);
                }
            }
#define QRED(x) do { x += __shfl_xor_sync(0xffffffffu, x, 1); \
                     x += __shfl_xor_sync(0xffffffffu, x, 2); } while (0)
            QRED(A0); QRED(B0); QRED(D0); QRED(C0); QRED(F0);
            QRED(A1); QRED(B1); QRED(D1); QRED(C1); QRED(F1);
#undef QRED
            if ((lane & 3) == 0) {
                atomicAdd(&g_rowA[gr0], A0); atomicAdd(&g_rowB[gr0], B0);
                atomicAdd(&g_rowD[gr0], D0); atomicAdd(&g_rowC[gr0], C0);
                atomicAdd(&g_rowF[gr0], F0);
                atomicAdd(&g_rowA[gr1], A1); atomicAdd(&g_rowB[gr1], B1);
                atomicAdd(&g_rowD[gr1], D1); atomicAdd(&g_rowC[gr1], C1);
                atomicAdd(&g_rowF[gr1], F1);
            }
        }
    } else {
        float cm[4][2];
#pragma unroll
        for (int ni = 0; ni < 4; ni++) { cm[ni][0] = -2.f; cm[ni][1] = -2.f; }
#pragma unroll
        for (int mi = 0; mi < 4; mi++) {
            int gr0 = m0 + wm + mi * 16 + tr;
            int gr1 = gr0 + 8;
            float mx0 = -2.f, mx1 = -2.f;
#pragma unroll
            for (int ni = 0; ni < 4; ni++) {
                int gc = n0 + wn + ni * 8 + tc;
                float v0 = (gc == gr0) ? -2.f : acc[mi][ni][0];
                float v1 = (gc + 1 == gr0) ? -2.f : acc[mi][ni][1];
                float v2 = (gc == gr1) ? -2.f : acc[mi][ni][2];
                float v3 = (gc + 1 == gr1) ? -2.f : acc[mi][ni][3];
                mx0 = fmaxf(mx0, fmaxf(v0, v1));
                mx1 = fmaxf(mx1, fmaxf(v2, v3));
                cm[ni][0] = fmaxf(cm[ni][0], fmaxf(v0, v2));
                cm[ni][1] = fmaxf(cm[ni][1], fmaxf(v1, v3));
            }
#pragma unroll
            for (int o = 1; o < 4; o <<= 1) {
                mx0 = fmaxf(mx0, __shfl_xor_sync(0xffffffffu, mx0, o));
                mx1 = fmaxf(mx1, __shfl_xor_sync(0xffffffffu, mx1, o));
            }
            if ((lane & 3) == 0) {
                atomicMax(&g_maxd[gr0], __float_as_int(mx0 + 2.0f));
                atomicMax(&g_maxd[gr1], __float_as_int(mx1 + 2.0f));
            }
        }
#pragma unroll
        for (int ni = 0; ni < 4; ni++) {
            float c0 = cm[ni][0], c1 = cm[ni][1];
#pragma unroll
            for (int o = 4; o < 32; o <<= 1) {
                c0 = fmaxf(c0, __shfl_xor_sync(0xffffffffu, c0, o));
                c1 = fmaxf(c1, __shfl_xor_sync(0xffffffffu, c1, o));
            }
            if (lane < 4) {
                int gc = n0 + wn + ni * 8 + lane * 2;
                atomicMax(&g_maxd[gc], __float_as_int(c0 + 2.0f));
                atomicMax(&g_maxd[gc + 1], __float_as_int(c1 + 2.0f));
            }
        }
    }
}

// ---------------- Sinkhorn r-update -------------------------------------------------
__global__ void r_update_kernel() {
    int k = blockIdx.x * blockDim.x + threadIdx.x;
    if (k < KPROT) {
        float r = g_r[k], s = g_S[k];
        g_r[k] = r / (r * s + SK_EPS);
        g_S[k] = 0.f;
    }
}

// ---------------- fused T+S pass: ONE Et traversal per Sinkhorn iteration -----------
// CTA owns 32 rows, staged one at a time in smem (cp.async double buffer).
// Per row: T = sum_k Et*r (from smem) -> c ; then S partials += Et*c (same smem row).
__global__ void __launch_bounds__(256, 2)
fused_pass_kernel(int rev) {
    __shared__ __align__(16) __half rowbuf[2][KPROT];   // 2 x 16KB
    __shared__ float cc;
    int tid = threadIdx.x;
    int blk = rev ? ((int)gridDim.x - 1 - blockIdx.x) : blockIdx.x;
    int m0 = blk * 32;
    uint32_t rb = smem_u32(&rowbuf[0][0]);

    // cache r for this thread's 32 columns (k = tid + j*256)
    float rc[32];
#pragma unroll
    for (int j = 0; j < 32; j++) rc[j] = g_r[tid + j * 256];
    float s[32];
#pragma unroll
    for (int j = 0; j < 32; j++) s[j] = 0.f;

#define LOAD_ROW(buf, m) do {                                                 \
    const __half* src = g_Et + (size_t)(m) * KPROT;                           \
    uint32_t dst = rb + (uint32_t)(buf) * 16384u;                             \
    _Pragma("unroll")                                                         \
    for (int i = 0; i < 4; i++) {                                             \
        int ch = tid + i * 256;                                               \
        cpasync16(dst + (uint32_t)ch * 16u, src + ch * 8);                    \
    }                                                                         \
    asm volatile("cp.async.commit_group;" ::: "memory");                     \
} while (0)

    LOAD_ROW(0, m0 + 0);
    LOAD_ROW(1, m0 + 1);

#pragma unroll 1
    for (int rr = 0; rr < 32; rr++) {
        if (rr < 31) asm volatile("cp.async.wait_group 1;" ::: "memory");
        else         asm volatile("cp.async.wait_group 0;" ::: "memory");
        __syncthreads();
        const __half* row = &rowbuf[rr & 1][0];
        // T partial over this thread's columns
        float t = 0.f;
#pragma unroll
        for (int j = 0; j < 32; j++)
            t = fmaf(__half2float(row[tid + j * 256]), rc[j], t);
        t = blockSum(t);
        if (tid == 0) {
            int m = m0 + rr;
            float co = g_c[m];
            float cn = co / (co * t + SK_EPS);
            g_c[m] = cn;
            cc = cn;
        }
        __syncthreads();
        float c = cc;
        // S partials from the same smem row
#pragma unroll
        for (int j = 0; j < 32; j++)
            s[j] = fmaf(__half2float(row[tid + j * 256]), c, s[j]);
        __syncthreads();   // everyone done reading buf (rr&1) before refill
        if (rr + 2 < 32) LOAD_ROW(rr & 1, m0 + rr + 2);
    }
#undef LOAD_ROW

#pragma unroll
    for (int j = 0; j < 32; j++) atomicAdd(&g_S[tid + j * 256], s[j]);
}

// ---------------- per-row loss finalize (uses row partials) -------------------------
__global__ void finalize_rows_kernel() {
    int m = blockIdx.x * blockDim.x + threadIdx.x;
    float tpt = 0.f, sptm = 0.f, mm = 0.f;
    if (m < MROWS) {
        float A = g_rowA[m], Bq = g_rowB[m], Dv = g_rowD[m];
        float Cv = g_rowC[m], F = g_rowF[m];
        float co = g_c[m];                    // c2
        float c3 = co / (co * A + SK_EPS);    // A == T3
        float lse_t = logf(Dv) + SHIFT;
        float lse_s = logf(F);
        tpt = c3 * (A * lse_t - Bq);
        mm = g_msk[m];
        sptm = mm * c3 * (A * lse_s - Cv * INV_ST);
    }
    tpt = blockSum(tpt);
    __syncthreads();
    sptm = blockSum(sptm);
    __syncthreads();
    mm = blockSum(mm);
    if (threadIdx.x == 0) {
        atomicAdd(&g_acc[0], tpt);
        atomicAdd(&g_acc[1], sptm);
        atomicAdd(&g_acc[2], mm);
    }
}

__global__ void koleo_kernel() {
    int k = blockIdx.x * blockDim.x + threadIdx.x;
    float term = 0.f;
    if (k < KPROT) {
        float g = __int_as_float(g_maxd[k]) - 2.0f;
        float d = sqrtf(fmaxf(2.f - 2.f * g, 0.f));
        term = logf(d + 1e-8f);
    }
    term = blockSum(term);
    if (threadIdx.x == 0) atomicAdd(&g_acc[3], term);
}

__global__ void finalize_kernel(float* __restrict__ out) {
    if (threadIdx.x == 0) {
        out[0] = g_acc[1] / fmaxf(g_acc[2], 1.f);
        out[1] = g_acc[0] * (1.f / (float)MROWS);
        out[2] = -g_acc[3] * (1.f / (float)KPROT);
    }
}

// ---------------- launch (single stream) ---------------------------------------------
extern "C" void kernel_launch(void* const* d_in, const int* in_sizes, int n_in,
                              void* d_out, int out_size) {
    int midx = -1;
    for (int i = 0; i < n_in; i++)
        if (in_sizes[i] == MROWS) { midx = i; break; }
    if (midx < 0) midx = 2;
    int others[3], no = 0;
    for (int i = 0; i < n_in && no < 3; i++)
        if (i != midx) others[no++] = i;

    const float* teacher = (const float*)d_in[others[0]];
    const float* student = (const float*)d_in[others[1]];
    const float* W       = (const float*)d_in[others[2]];
    const void*  mask    = d_in[midx];

    detect_mask_kernel<<<1, 256>>>((const unsigned char*)mask);
    build_mask_kernel<<<32, 256>>>(mask);
    init_kernel<<<32, 256>>>();

    norm_all_kernel<<<dim3(MROWS / 8, 3), 256>>>(teacher, student, W);

    // teacher GEMM -> Et + fused S1 colsum (writes ascending row-blocks, ends HIGH)
    gemm_teacher_kernel<<<dim3(KPROT / 128, MROWS / 128), 256>>>();

    // Sinkhorn with fused T+S passes (one Et traversal per iteration):
    // r1 ; pass A (T1->c1, S2) DESC ; r2 ; pass B (T2->c2, S3) ASC ; r3
    r_update_kernel<<<KPROT / 256, 256>>>();
    fused_pass_kernel<<<MROWS / 32, 256>>>(1);
    r_update_kernel<<<KPROT / 256, 256>>>();
    fused_pass_kernel<<<MROWS / 32, 256>>>(0);
    r_update_kernel<<<KPROT / 256, 256>>>();

    // student GEMM with fused loss epilogue (needs r3, c2, Et; y-reversed) + koleo GEMM
    gemm_sk_kernel<<<dim3(KPROT / 128, MROWS / 128, 2), 256>>>();

    finalize_rows_kernel<<<MROWS / 256, 256>>>();
    koleo_kernel<<<KPROT / 256, 256>>>();
    finalize_kernel<<<1, 32>>>((float*)d_out);
    (void)out_size;
}